// round 13
// baseline (speedup 1.0000x reference)
#include <cuda_runtime.h>
#include <cstdint>

// (B, D, H, W) = (2, 192, 192, 192) fp32
#define DD 192
#define HH 192
#define WW 192
#define PLANE 36864
#define VOL   7077888

#define NT 256
// raw stage: [3 sets][2 fld][24 rows][44]
#define ST_ROW 44
#define ST_FIELD 1056
#define ST_SLICE 2112
// H-sums: [2 par][3 fld][16 rows][44]
#define HS_STR 44
#define HS_FLD 704
#define HS_PAR 2112
// HW-sums: [2 par][3 fld][16 rows][36]
#define HW_STR 36
#define HW_FLD 576
#define HW_PAR 1728

#define INV_VOL (1.0f/729.0f)
#define EPS 1e-5f

#define SMEM_FLOATS (3*ST_SLICE + 2*HS_PAR + 2*HW_PAR)   // 14016
#define SMEM_BYTES  (SMEM_FLOATS*4)                      // 56064 -> 2 CTAs/SM

// R13: H-then-W separability + 4-stage skewed pipeline
//   iter k: fill(k+2) | H(k) raw->Hsum | W(k-1) Hsum->HW | D(k-2) HW->ring->out
__global__ void __launch_bounds__(NT, 2)
lncc_fused8(const float* __restrict__ gt, const float* __restrict__ gp,
            float* __restrict__ out)
{
    extern __shared__ float sm[];
    float* stg  = sm;                       // raw slices
    float* hsum = sm + 3*ST_SLICE;          // H-sums
    float* hw   = hsum + 2*HS_PAR;          // HW-sums

    const int tid = threadIdx.x;
    const int bx = blockIdx.x;
    const int wt = bx % 6;
    const int ht = (bx/6) % 12;
    const int dc = (bx/72) % 2;
    const int bb = bx/144;
    const int w0 = wt*32, h0 = ht*16, d0 = dc*96;
    const int gvol = bb*VOL;

    // zero raw stages once: OOB halo lanes never overwritten -> SAME padding
    for (int i = tid; i < 3*ST_SLICE; i += NT) stg[i] = 0.f;

    const uint32_t stg_base = (uint32_t)__cvta_generic_to_shared(stg);

    // ---- fill geometry: 480 tasks = (2 fld x 24 rows) x 10 float4 chunks ----
    const float* fsrc[2]; uint32_t fdst[2]; bool fok[2];
#pragma unroll
    for (int k2 = 0; k2 < 2; ++k2) {
        const int task = tid + k2*NT;
        bool ok = task < 480;
        const int chunk = task % 10;
        const int rowf  = task / 10;
        const int fld   = rowf >= 24 ? 1 : 0;
        const int row   = rowf - fld*24;
        const int gh = h0 - 4 + row;
        const int gw = w0 - 4 + chunk*4;
        ok = ok && (unsigned)gh < HH && (unsigned)gw < WW;
        fok[k2]  = ok;
        fsrc[k2] = (fld ? gp : gt) + (gvol + gh*WW + gw);
        fdst[k2] = stg_base + (uint32_t)(fld*ST_FIELD + row*ST_ROW + chunk*4)*4u;
    }

    auto fill = [&](int j) {
        const int dz = d0 - 4 + j;
        if ((unsigned)dz < DD) {
            const int off = dz*PLANE;
            const uint32_t dsb = (uint32_t)((j%3)*ST_SLICE)*4u;
#pragma unroll
            for (int k2 = 0; k2 < 2; ++k2)
                if (fok[k2])
                    asm volatile("cp.async.cg.shared.global [%0], [%1], 16;"
                                 :: "r"(fdst[k2]+dsb), "l"(fsrc[k2]+off));
        }
        asm volatile("cp.async.commit_group;");
    };

    // ---- H-stage: 80 tasks = 40 cols x 2 h-chunks of 8 outputs (warps 0-2) --
    const bool hact = tid < 80;
    const int hcol = tid % 40;
    const int hch  = (tid / 40) << 3;            // 0 or 8
    const int h_rd = hch*ST_ROW + hcol;
    const int h_wr = hch*HS_STR + hcol;

    auto hstage = [&](int j) {
        if (!hact) return;
        float* o = hsum + (j&1)*HS_PAR + h_wr;
        const int dz = d0 - 4 + j;
        if ((unsigned)dz < DD) {
            const float* rt = stg + (j%3)*ST_SLICE + h_rd;
            float t[16], p[16];
#pragma unroll
            for (int r = 0; r < 16; ++r) {
                t[r] = rt[r*ST_ROW];
                p[r] = rt[ST_FIELD + r*ST_ROW];
            }
            float s0 = 0.f, s1 = 0.f, s2 = 0.f;
#pragma unroll
            for (int r = 0; r < 9; ++r) {
                s0 += t[r]; s1 += p[r]; s2 = fmaf(t[r], p[r], s2);
            }
            o[0] = s0; o[HS_FLD] = s1; o[2*HS_FLD] = s2;
#pragma unroll
            for (int q = 1; q < 8; ++q) {
                s0 += t[8+q] - t[q-1];
                s1 += p[8+q] - p[q-1];
                s2 = fmaf(t[8+q], p[8+q], s2);
                s2 = fmaf(-t[q-1], p[q-1], s2);
                o[q*HS_STR] = s0;
                o[HS_FLD + q*HS_STR] = s1;
                o[2*HS_FLD + q*HS_STR] = s2;
            }
        } else {
#pragma unroll
            for (int q = 0; q < 8; ++q) {
                o[q*HS_STR] = 0.f;
                o[HS_FLD + q*HS_STR] = 0.f;
                o[2*HS_FLD + q*HS_STR] = 0.f;
            }
        }
    };

    // ---- W-stage: 64 tasks = 16 rows x 4 segs of 8 outputs (warps 3-4) ------
    const bool wact = (tid >= 96) && (tid < 160);
    const int wi   = tid - 96;
    const int wrow = wi & 15;
    const int wsg8 = (wi >> 4) << 3;             // 0,8,16,24
    const int w_rd = wrow*HS_STR + wsg8;
    const int w_wr = wrow*HW_STR + wsg8;

    auto wstage = [&](int j) {
        if (!wact) return;
        const int par = j & 1;
        const float* in = hsum + par*HS_PAR + w_rd;
        float* o = hw + par*HW_PAR + w_wr;
#pragma unroll
        for (int f = 0; f < 3; ++f) {
            const float4 V0 = *(const float4*)(in + f*HS_FLD);
            const float4 V1 = *(const float4*)(in + f*HS_FLD + 4);
            const float4 V2 = *(const float4*)(in + f*HS_FLD + 8);
            const float4 V3 = *(const float4*)(in + f*HS_FLD + 12);
            const float u[16] = {V0.x,V0.y,V0.z,V0.w, V1.x,V1.y,V1.z,V1.w,
                                 V2.x,V2.y,V2.z,V2.w, V3.x,V3.y,V3.z,V3.w};
            float s = 0.f;
#pragma unroll
            for (int r = 0; r < 9; ++r) s += u[r];
            float res[8];
            res[0] = s;
#pragma unroll
            for (int q = 1; q < 8; ++q) { s += u[8+q] - u[q-1]; res[q] = s; }
            *(float4*)(o + f*HW_FLD)     = make_float4(res[0],res[1],res[2],res[3]);
            *(float4*)(o + f*HW_FLD + 4) = make_float4(res[4],res[5],res[6],res[7]);
        }
    };

    // ---- D-stage geometry: all threads, 2 h-rows each ----
    const int tx = tid & 31, ty = tid >> 5;
    const int rb = ty << 1;
    const int d_rd = rb*HW_STR + tx;
    const int obase = gvol + (h0 + rb)*WW + w0 + tx;

    float ring[48], S[6];
#pragma unroll
    for (int q = 0; q < 48; ++q) ring[q] = 0.f;
#pragma unroll
    for (int q = 0; q < 6; ++q) S[q] = 0.f;

    __syncthreads();            // raw zeros visible before cp.async fills
    fill(0);
    fill(1);

    // ---- prologue iterations k = 0, 1 ----
    asm volatile("cp.async.wait_group 1;");
    __syncthreads();
    fill(2);
    hstage(0);

    asm volatile("cp.async.wait_group 1;");
    __syncthreads();
    fill(3);
    hstage(1);
    wstage(0);

    // ---- main: k = 2..105 (13 blocks x 8), D slice j = k-2 = 0..103 ----
    for (int b = 0; b < 13; ++b) {
#pragma unroll
        for (int ph = 0; ph < 8; ++ph) {
            const int k = 2 + b*8 + ph;
            asm volatile("cp.async.wait_group 1;");
            __syncthreads();
            if (k <= 101) fill(k + 2);
            else asm volatile("cp.async.commit_group;");
            if (k <= 103) hstage(k);
            if (k <= 104) wstage(k - 1);

            // D-stage: slice j = k-2 (ring slot = ph, compile-time)
            const int j = k - 2;
            const float* hp = hw + (j&1)*HW_PAR + d_rd;
            const float A0 = hp[0];
            const float A1 = hp[HW_FLD];
            const float A2 = hp[2*HW_FLD];
            const float B0 = hp[HW_STR];
            const float B1 = hp[HW_FLD + HW_STR];
            const float B2 = hp[2*HW_FLD + HW_STR];
            S[0] += A0; S[1] += A1; S[2] += A2;
            S[3] += B0; S[4] += B1; S[5] += B2;
            if (b > 0) {                         // j >= 8
                const float ca = S[2] - S[1]*S[0]*INV_VOL;
                const float cb = S[5] - S[4]*S[3]*INV_VOL;
                const int o = obase + (d0 + j - 8)*PLANE;
                out[o]      = fmaf(ca, ca, EPS);
                out[o + WW] = fmaf(cb, cb, EPS);
            }
            S[0] -= ring[ph*6+0]; S[1] -= ring[ph*6+1]; S[2] -= ring[ph*6+2];
            S[3] -= ring[ph*6+3]; S[4] -= ring[ph*6+4]; S[5] -= ring[ph*6+5];
            ring[ph*6+0] = A0; ring[ph*6+1] = A1; ring[ph*6+2] = A2;
            ring[ph*6+3] = B0; ring[ph*6+4] = B1; ring[ph*6+5] = B2;
        }
    }
}

extern "C" void kernel_launch(void* const* d_in, const int* in_sizes, int n_in,
                              void* d_out, int out_size) {
    const float* y_true = (const float*)d_in[0];
    const float* y_pred = (const float*)d_in[1];
    float* out = (float*)d_out;

    cudaFuncSetAttribute(lncc_fused8,
                         cudaFuncAttributeMaxDynamicSharedMemorySize, SMEM_BYTES);

    // 6 w-tiles x 12 h-tiles x 2 d-chunks x 2 batches = 288 blocks (2 CTAs/SM)
    lncc_fused8<<<288, NT, SMEM_BYTES>>>(y_true, y_pred, out);
}

// round 14
// speedup vs baseline: 1.0262x; 1.0262x over previous
#include <cuda_runtime.h>
#include <cstdint>

// (B, D, H, W) = (2, 192, 192, 192) fp32
#define DD 192
#define HH 192
#define WW 192
#define PLANE 36864
#define VOL   7077888

#define NT 256
// raw stage: [2 sets][2 sl][2 fld][24 rows][44]
#define ST_ROW 44
#define ST_FIELD 1056
#define ST_SLICE 2112
#define ST_SET   4224
// W-sums: [2 par][2 sl][3 fld][24 rows][33]
#define WS_STR 33
#define WS_FLD 792
#define WS_SL  2376
#define WS_PAR 4752
// HW-sums: [2 par][2 sl][3 fld][16 rows][32]
#define HW_STR 32
#define HW_FLD 512
#define HW_SL  1536
#define HW_PAR 3072

#define INV_VOL (1.0f/729.0f)
#define EPS 1e-5f

#define SMEM_FLOATS (2*ST_SET + 2*WS_PAR + 2*HW_PAR)   // 24096
#define SMEM_BYTES  (SMEM_FLOATS*4)                    // 96384 -> 2 CTAs/SM

// R14: pair-batched 4-stage pipeline with materialized HW sums.
//   region i: fill(pair i+1) | W(pair i) warps0-5 | H(pair i-1) warps6-7 | D(pair i-2) all
__global__ void __launch_bounds__(NT, 2)
lncc_fused9(const float* __restrict__ gt, const float* __restrict__ gp,
            float* __restrict__ out)
{
    extern __shared__ float sm[];
    float* stg  = sm;                     // raw slices
    float* wsum = sm + 2*ST_SET;          // W-sums
    float* hws  = wsum + 2*WS_PAR;        // HW-sums

    const int tid = threadIdx.x;
    const int bx = blockIdx.x;
    const int wt = bx % 6;
    const int ht = (bx/6) % 12;
    const int dc = (bx/72) % 2;
    const int bb = bx/144;
    const int w0 = wt*32, h0 = ht*16, d0 = dc*96;
    const int gvol = bb*VOL;

    // zero raw stages once: OOB halo lanes never overwritten -> SAME padding
    for (int i = tid; i < 2*ST_SET; i += NT) stg[i] = 0.f;

    const uint32_t stg_base = (uint32_t)__cvta_generic_to_shared(stg);

    // ---- fill geometry: 480 chunk-tasks/slice = 48 rowf x 10 float4 ----
    const float* fsrc[2]; uint32_t fdst[2]; bool fok[2];
#pragma unroll
    for (int k2 = 0; k2 < 2; ++k2) {
        const int task = tid + k2*NT;
        bool ok = task < 480;
        const int chunk = task % 10;
        const int rowf  = task / 10;
        const int fld   = rowf >= 24 ? 1 : 0;
        const int row   = rowf - fld*24;
        const int gh = h0 - 4 + row;
        const int gw = w0 - 4 + chunk*4;
        ok = ok && (unsigned)gh < HH && (unsigned)gw < WW;
        fok[k2]  = ok;
        fsrc[k2] = (fld ? gp : gt) + (gvol + gh*WW + gw);
        fdst[k2] = stg_base + (uint32_t)(fld*ST_FIELD + row*ST_ROW + chunk*4)*4u;
    }

    auto fill_pair = [&](int p) {
        const int set = p & 1;
#pragma unroll
        for (int sl = 0; sl < 2; ++sl) {
            const int dz = d0 - 4 + 2*p + sl;
            if ((unsigned)dz < DD) {
                const int off = dz*PLANE;
                const uint32_t dsb = (uint32_t)(set*ST_SET + sl*ST_SLICE)*4u;
#pragma unroll
                for (int k2 = 0; k2 < 2; ++k2)
                    if (fok[k2])
                        asm volatile("cp.async.cg.shared.global [%0], [%1], 16;"
                                     :: "r"(fdst[k2]+dsb), "l"(fsrc[k2]+off));
            }
        }
        asm volatile("cp.async.commit_group;");
    };

    // ---- W geometry: 192 tasks/pair = 2 sl x 24 rows x 4 segs of 8 ----
    const bool wact = tid < 192;
    const int wsl  = tid >= 96 ? 1 : 0;
    const int wsub = tid - wsl*96;
    const int wr   = wsub >> 2, ws8 = (wsub & 3) << 3;
    const int w_rd = wsl*ST_SLICE + wr*ST_ROW + ws8;
    const int w_wr = wsl*WS_SL + wr*WS_STR + ws8;

    auto wstage = [&](int p) {
        if (!wact) return;
        const int dz = d0 - 4 + 2*p + wsl;
        float* o = wsum + (p&1)*WS_PAR + w_wr;
        if ((unsigned)dz < DD) {
            const float* pt = stg + (p&1)*ST_SET + w_rd;
            const float4 T0 = ((const float4*)pt)[0];
            const float4 T1 = ((const float4*)pt)[1];
            const float4 T2 = ((const float4*)pt)[2];
            const float4 T3 = ((const float4*)pt)[3];
            const float* pq = pt + ST_FIELD;
            const float4 P0 = ((const float4*)pq)[0];
            const float4 P1 = ((const float4*)pq)[1];
            const float4 P2 = ((const float4*)pq)[2];
            const float4 P3 = ((const float4*)pq)[3];
            const float t[16] = {T0.x,T0.y,T0.z,T0.w, T1.x,T1.y,T1.z,T1.w,
                                 T2.x,T2.y,T2.z,T2.w, T3.x,T3.y,T3.z,T3.w};
            const float p2[16] = {P0.x,P0.y,P0.z,P0.w, P1.x,P1.y,P1.z,P1.w,
                                  P2.x,P2.y,P2.z,P2.w, P3.x,P3.y,P3.z,P3.w};
            float s0 = 0.f, s1 = 0.f, s2 = 0.f;
#pragma unroll
            for (int k = 0; k < 9; ++k) {
                s0 += t[k]; s1 += p2[k]; s2 = fmaf(t[k], p2[k], s2);
            }
            o[0] = s0; o[WS_FLD] = s1; o[2*WS_FLD] = s2;
#pragma unroll
            for (int q = 1; q < 8; ++q) {
                s0 += t[8+q] - t[q-1];
                s1 += p2[8+q] - p2[q-1];
                s2 = fmaf(t[8+q], p2[8+q], s2);
                s2 = fmaf(-t[q-1], p2[q-1], s2);
                o[q] = s0; o[WS_FLD+q] = s1; o[2*WS_FLD+q] = s2;
            }
        } else {
#pragma unroll
            for (int q = 0; q < 8; ++q) {
                o[q] = 0.f; o[WS_FLD+q] = 0.f; o[2*WS_FLD+q] = 0.f;
            }
        }
    };

    // ---- H geometry: 64 tasks/pair = 2 sl x 32 cols; 16-output h-slide ----
    const bool hact = tid >= 192;
    const int hi  = tid - 192;              // 0..63
    const int hsl = hi >= 32 ? 1 : 0;
    const int hc  = hi & 31;
    const int h_rd = hsl*WS_SL + hc;
    const int h_wr = hsl*HW_SL + hc;

    auto hstage = [&](int p) {
        if (!hact) return;
        const float* in = wsum + (p&1)*WS_PAR + h_rd;
        float* o = hws + (p&1)*HW_PAR + h_wr;
#pragma unroll
        for (int f = 0; f < 3; ++f) {
            float u[24];
#pragma unroll
            for (int r = 0; r < 24; ++r) u[r] = in[f*WS_FLD + r*WS_STR];
            float s = ((u[0]+u[1])+(u[2]+u[3]))+((u[4]+u[5])+(u[6]+u[7]))+u[8];
            o[f*HW_FLD] = s;
#pragma unroll
            for (int q = 1; q < 16; ++q) {
                s += u[8+q] - u[q-1];
                o[f*HW_FLD + q*HW_STR] = s;
            }
        }
    };

    // ---- D geometry: all threads, 2 h-rows each ----
    const int tx = tid & 31, ty = tid >> 5;
    const int rb = ty << 1;
    const int d_rd = rb*HW_STR + tx;
    const int obase = gvol + (h0 + rb)*WW + w0 + tx;

    float ring[48], S[6];
#pragma unroll
    for (int q = 0; q < 48; ++q) ring[q] = 0.f;
#pragma unroll
    for (int q = 0; q < 6; ++q) S[q] = 0.f;

#define D_INGEST(HB, SL, PH, DOUT, DVAL) do {                                \
    const float* q_ = (HB) + (SL)*HW_SL;                                     \
    const float A0 = q_[0];                                                  \
    const float A1 = q_[HW_FLD];                                             \
    const float A2 = q_[2*HW_FLD];                                           \
    const float B0 = q_[HW_STR];                                             \
    const float B1 = q_[HW_FLD + HW_STR];                                    \
    const float B2 = q_[2*HW_FLD + HW_STR];                                  \
    S[0]+=A0; S[1]+=A1; S[2]+=A2; S[3]+=B0; S[4]+=B1; S[5]+=B2;              \
    if (DOUT) {                                                              \
        const float ca = S[2]-S[1]*S[0]*INV_VOL;                             \
        const float cb = S[5]-S[4]*S[3]*INV_VOL;                             \
        const int oo = obase + (DVAL)*PLANE;                                 \
        out[oo]    = fmaf(ca,ca,EPS);                                        \
        out[oo+WW] = fmaf(cb,cb,EPS);                                        \
    }                                                                        \
    S[0]-=ring[(PH)*6+0]; S[1]-=ring[(PH)*6+1]; S[2]-=ring[(PH)*6+2];        \
    S[3]-=ring[(PH)*6+3]; S[4]-=ring[(PH)*6+4]; S[5]-=ring[(PH)*6+5];        \
    ring[(PH)*6+0]=A0; ring[(PH)*6+1]=A1; ring[(PH)*6+2]=A2;                 \
    ring[(PH)*6+3]=B0; ring[(PH)*6+4]=B1; ring[(PH)*6+5]=B2;                 \
} while(0)

    __syncthreads();                 // raw zeros visible
    fill_pair(0);

    // region 0
    asm volatile("cp.async.wait_group 0;");
    __syncthreads();
    fill_pair(1);
    wstage(0);

    // region 1
    asm volatile("cp.async.wait_group 0;");
    __syncthreads();
    fill_pair(2);
    wstage(1);
    hstage(0);

    // main regions i = 2..53: D processes pairs 0..51 (slices 0..103)
    for (int b = 0; b < 13; ++b) {
#pragma unroll
        for (int ii = 0; ii < 4; ++ii) {
            const int i = 2 + b*4 + ii;
            asm volatile("cp.async.wait_group 0;");
            __syncthreads();
            if (i <= 50) fill_pair(i + 1);
            if (i <= 51) wstage(i);
            if (i <= 52) hstage(i - 1);

            const int p = i - 2;
            const bool dout = (i >= 6);            // slices t >= 8
            const float* hb = hws + ((p&1) ? HW_PAR : 0) + d_rd;
            D_INGEST(hb, 0, (2*ii)&7,   dout, d0 + 2*p - 8);
            D_INGEST(hb, 1, (2*ii+1)&7, dout, d0 + 2*p - 7);
        }
    }
#undef D_INGEST
}

extern "C" void kernel_launch(void* const* d_in, const int* in_sizes, int n_in,
                              void* d_out, int out_size) {
    const float* y_true = (const float*)d_in[0];
    const float* y_pred = (const float*)d_in[1];
    float* out = (float*)d_out;

    cudaFuncSetAttribute(lncc_fused9,
                         cudaFuncAttributeMaxDynamicSharedMemorySize, SMEM_BYTES);

    // 6 w-tiles x 12 h-tiles x 2 d-chunks x 2 batches = 288 blocks (2 CTAs/SM)
    lncc_fused9<<<288, NT, SMEM_BYTES>>>(y_true, y_pred, out);
}